// round 16
// baseline (speedup 1.0000x reference)
#include <cuda_runtime.h>
#include <cuda_fp16.h>
#include <math.h>

typedef unsigned char u8;
typedef unsigned short u16t;

// ---------------- problem constants ----------------
#define Bb   64
#define Hh   15
#define Tt   16
#define Ff   32
#define Dd   512
#define NHh  8
#define Ll   4
#define DFFf 2048
#define NTOK (Bb*Tt*Ff)          // 32768 rows
#define EPSc 1e-7f
#define WSc   16.0f              // fp8 weight scale
#define IWSc  0.0625f

// fp8 transposed-weight pool offsets (bytes); each weight stored [N,K]
#define OFF_FAQKV 0
#define SZ_FAQKV  (4*512*1536)
#define OFF_FAWO  (OFF_FAQKV + SZ_FAQKV)
#define SZ_FAWO   (4*512*512)
#define OFF_HAQKV (OFF_FAWO + SZ_FAWO)
#define OFF_HAWO  (OFF_HAQKV + SZ_FAQKV)
#define OFF_FFN1  (OFF_HAWO + SZ_FAWO)
#define SZ_FFN1   (4*512*2048)
#define OFF_FFN2  (OFF_FFN1 + SZ_FFN1)
#define OFF_POOLW (OFF_FFN2 + SZ_FFN1)
#define SZ_POOLW  (512*512)
#define OFF_PROJW (OFF_POOLW + SZ_POOLW)
#define SZ_PROJW  (1024*512)
#define OFF_EW1   (OFF_PROJW + SZ_PROJW)
#define SZ_EW1    (512*512)
#define W8_TOTAL  (OFF_EW1 + SZ_EW1)

// GEMM smem — 3-stage
#define SA8 80                               // smem row stride (bytes)
#define STG_B (2*128*SA8)                    // A+B per stage = 20480 B
#define NSTG 3
#define GSM_B (NSTG*STG_B)                   // 61440 B dynamic smem

// ---------------- scratch (device globals) ----------------
__device__ __half g_seqh[NTOK*Dd];
__device__ __half g_qkvh[NTOK*3*Dd];         // fp16 qkv / pool tanh buf
__device__ u8     g_a8 [NTOK*Dd];
__device__ u8     g_f8 [NTOK*DFFf];
__device__ u8     g_w8 [W8_TOTAL];
__device__ float  g_s  [NTOK];
__device__ float  g_pool[Bb*Tt*Dd];
__device__ u8     g_comb8[Bb*Hh*2*Dd];
__device__ float  g_feat[Bb*Hh*Dd];
__device__ u8     g_feat8[Bb*Hh*Dd];
__device__ float  g_u  [Bb*Hh*Dd];

// ---------------- helpers ----------------
__device__ __forceinline__ float warp_sum(float v){
#pragma unroll
    for (int o = 16; o > 0; o >>= 1) v += __shfl_xor_sync(0xffffffffu, v, o);
    return v;
}
__device__ __forceinline__ float gelu_f(float x){
    float x3 = x*x*x;
    float t  = tanhf(0.7978845608028654f*(x + 0.044715f*x3));
    return 0.5f*x*(1.f + t);
}
__device__ __forceinline__ float gelu_grad(float x){
    float x2 = x*x;
    float t  = tanhf(0.7978845608028654f*(x + 0.044715f*x2*x));
    float sech2 = 1.f - t*t;
    return 0.5f*(1.f + t) + 0.5f*x*sech2*0.7978845608028654f*(1.f + 3.f*0.044715f*x2);
}
__device__ __forceinline__ unsigned smem_u32(const void* p){
    return (unsigned)__cvta_generic_to_shared(p);
}
__device__ __forceinline__ unsigned pack_h2(float a, float b){
    unsigned lo = (unsigned)__half_as_ushort(__float2half_rn(a));
    unsigned hi = (unsigned)__half_as_ushort(__float2half_rn(b));
    return lo | (hi << 16);
}
__device__ __forceinline__ u16t e4m3_2(float lo, float hi){
    u16t r;
    asm("cvt.rn.satfinite.e4m3x2.f32 %0, %1, %2;" : "=h"(r) : "f"(hi), "f"(lo));
    return r;
}
__device__ __forceinline__ float2 h2f(unsigned h){
    return __half22float2(*(__half2*)&h);
}
__device__ __forceinline__ void ldsm_x4(unsigned& r0, unsigned& r1, unsigned& r2, unsigned& r3, unsigned a){
    asm volatile("ldmatrix.sync.aligned.m8n8.x4.shared.b16 {%0,%1,%2,%3},[%4];\n"
        : "=r"(r0), "=r"(r1), "=r"(r2), "=r"(r3) : "r"(a));
}
__device__ __forceinline__ void mma_e4m3(float* c, const unsigned* a, unsigned b0, unsigned b1){
    asm volatile("mma.sync.aligned.m16n8k32.row.col.f32.e4m3.e4m3.f32 "
        "{%0,%1,%2,%3}, {%4,%5,%6,%7}, {%8,%9}, {%0,%1,%2,%3};\n"
        : "+f"(c[0]), "+f"(c[1]), "+f"(c[2]), "+f"(c[3])
        : "r"(a[0]), "r"(a[1]), "r"(a[2]), "r"(a[3]), "r"(b0), "r"(b1));
}
__device__ __forceinline__ void cp_async16(unsigned dst, const void* src, int srcsize){
    asm volatile("cp.async.cg.shared.global [%0], [%1], 16, %2;\n" :: "r"(dst), "l"(src), "r"(srcsize));
}
__device__ __forceinline__ void cp_commit(){ asm volatile("cp.async.commit_group;\n"); }
template<int N> __device__ __forceinline__ void cp_wait(){
    asm volatile("cp.async.wait_group %0;\n" :: "n"(N));
}

// ---------------- weight transpose+convert: [K,N] f32 -> [N,K] fp8 x16 ----------------
__global__ __launch_bounds__(256)
void wcvt_kernel(const float* __restrict__ in0, u8* __restrict__ out0,
                 const float* __restrict__ in1, u8* __restrict__ out1,
                 int K, int N, int L0)
{
    __shared__ float t[32][33];
    int z = blockIdx.z;
    const float* inz;
    u8* outz;
    if (z < L0) { inz = in0 + (size_t)z * K * N;        outz = out0 + (size_t)z * K * N; }
    else        { inz = in1 + (size_t)(z - L0) * K * N; outz = out1 + (size_t)(z - L0) * K * N; }
    int kb = blockIdx.y*32, nb = blockIdx.x*32;
    int tx = threadIdx.x & 31, ty = threadIdx.x >> 5;
#pragma unroll
    for (int j = 0; j < 32; j += 8)
        t[ty+j][tx] = inz[(size_t)(kb+ty+j)*N + nb+tx];
    __syncthreads();
#pragma unroll
    for (int j = 0; j < 32; j += 8) {
        float v = t[tx][ty+j] * WSc;
        u16t p = e4m3_2(v, 0.f);
        outz[(size_t)(nb+ty+j)*K + kb+tx] = (u8)(p & 0xff);
    }
}

// ---------------- embedding -> fp16 seq ----------------
__global__ __launch_bounds__(256)
void embed_kernel(const float* __restrict__ x_cont, const int* __restrict__ x_cat,
                  const float* __restrict__ emb_w, const float* __restrict__ emb_b,
                  const float* __restrict__ cat_emb, const float* __restrict__ cls,
                  __half* __restrict__ seq)
{
    int idx = blockIdx.x*256 + threadIdx.x;
    int d  = (idx & 255) * 2;
    int f  = (idx >> 8)  & 31;
    int t  = (idx >> 13) & 15;
    int b  =  idx >> 17;
    float v0, v1;
    if (t == Tt-1) {
        float2 c = *(const float2*)(cls + f*Dd + d);
        v0 = c.x; v1 = c.y;
    } else if (f < 24) {
        float xc = x_cont[(b*Hh + t)*24 + f];
        float2 w = *(const float2*)(emb_w + f*Dd + d);
        float2 e = *(const float2*)(emb_b + f*Dd + d);
        v0 = xc*w.x + e.x; v1 = xc*w.y + e.y;
    } else {
        int fc = f - 24;
        int c  = x_cat[(b*Hh + t)*8 + fc];
        float2 e = *(const float2*)(cat_emb + ((size_t)fc*50 + c)*Dd + d);
        v0 = e.x; v1 = e.y;
    }
    ((unsigned*)seq)[idx] = pack_h2(v0, v1);
}

// ---------------- layernorm: warp per row, g/b cached in smem, fp16 in, fp8 out ----------------
__global__ __launch_bounds__(256)
void ln2_kernel(const __half* __restrict__ X, u8* __restrict__ Y,
                const float* __restrict__ gg, const float* __restrict__ bb)
{
    __shared__ float sg[Dd], sb[Dd];
    const int tid  = threadIdx.x;
    if (tid < 128) {
        ((float4*)sg)[tid] = ((const float4*)gg)[tid];
    } else {
        ((float4*)sb)[tid - 128] = ((const float4*)bb)[tid - 128];
    }
    __syncthreads();

    const int row  = blockIdx.x*8 + (tid >> 5);
    const int lane = tid & 31;
    const uint4* xr = (const uint4*)(X + (size_t)row*Dd);
    float x[16];
    float s = 0.f, s2 = 0.f;
#pragma unroll
    for (int j = 0; j < 2; j++) {
        uint4 u = xr[lane + 32*j];
        float2 p0 = h2f(u.x), p1 = h2f(u.y), p2 = h2f(u.z), p3 = h2f(u.w);
        x[j*8+0]=p0.x; x[j*8+1]=p0.y; x[j*8+2]=p1.x; x[j*8+3]=p1.y;
        x[j*8+4]=p2.x; x[j*8+5]=p2.y; x[j*8+6]=p3.x; x[j*8+7]=p3.y;
    }
#pragma unroll
    for (int i = 0; i < 16; i++) { s += x[i]; s2 += x[i]*x[i]; }
#pragma unroll
    for (int o = 16; o > 0; o >>= 1) {
        s  += __shfl_xor_sync(0xffffffffu, s,  o);
        s2 += __shfl_xor_sync(0xffffffffu, s2, o);
    }
    float mean = s * (1.f/Dd);
    float var  = s2 * (1.f/Dd) - mean*mean;
    float inv  = rsqrtf(var + 1e-5f);
#pragma unroll
    for (int j = 0; j < 2; j++) {
        int base = (lane + 32*j)*8;
        u16t h[4];
#pragma unroll
        for (int q = 0; q < 4; q++) {
            h[q] = e4m3_2((x[j*8+q*2  ]-mean)*inv*sg[base+q*2  ] + sb[base+q*2  ],
                          (x[j*8+q*2+1]-mean)*inv*sg[base+q*2+1] + sb[base+q*2+1]);
        }
        uint2 o;
        o.x = (unsigned)h[0] | ((unsigned)h[1] << 16);
        o.y = (unsigned)h[2] | ((unsigned)h[3] << 16);
        *(uint2*)(Y + (size_t)row*Dd + base) = o;
    }
}

// ---------------- fp8 tensor-core GEMM: 256 threads, 8 warps, warp tile 64x32 ----------------
// C[M,N] (+)= act(A[M,K] @ Wt[N,K]^T * 1/16 + bias); A,Wt e4m3.
// Block 128x128x64, 8 warps (2m x 4n), warp 64x32, mma m16n8k32, 3-stage cp.async.
// Requires N % 128 == 0, K % 64 == 0, K >= 192.
template<int ACT, int COUT>   // ACT: 0 none, 1 gelu, 2 tanh; COUT: 0 f32, 1 f16, 2 fp8
__global__ __launch_bounds__(256, 2)
void qgemm_kernel(const u8* __restrict__ A, const u8* __restrict__ Wt,
                  void* __restrict__ Cv, int M, int N, int K,
                  const float* __restrict__ bias, int accum, u8* __restrict__ C8dup)
{
    extern __shared__ __align__(16) u8 gsm[];
    const int tid  = threadIdx.x;
    const int lane = tid & 31;
    const int warp = tid >> 5;
    const int wm0  = (warp & 1) * 64;
    const int wn0  = (warp >> 1) * 32;
    const int bm   = blockIdx.y * 128;
    const int bn   = blockIdx.x * 128;
    const int g    = lane >> 2;
    const int tg   = lane & 3;

    // staging: 256 threads x 2 chunks of 16B each for A and B
    const int s_r0 = tid >> 2;           // 0..63, +64 second iter
    const int s_kc = (tid & 3) * 16;

    // ldsm lane coords
    const int a_row = lane & 15;
    const int a_byt = (lane >> 4) * 16;
    const int b_row = ((lane >> 4) & 1) * 8 + (lane & 7);
    const int b_byt = ((lane >> 3) & 1) * 16;

    float acc[4][4][4];
#pragma unroll
    for (int i = 0; i < 4; i++)
#pragma unroll
        for (int j = 0; j < 4; j++)
#pragma unroll
            for (int q = 0; q < 4; q++) acc[i][j][q] = 0.f;

    const int nc = K >> 6;

    auto issue = [&](int c){
        u8* As = gsm + (c % NSTG)*STG_B;
        u8* Bs = As + 128*SA8;
        int k0 = c << 6;
#pragma unroll
        for (int it = 0; it < 2; it++) {
            int r = s_r0 + it*64;
            int gr = bm + r;
            cp_async16(smem_u32(As + r*SA8 + s_kc), A + (size_t)gr*K + k0 + s_kc,
                       gr < M ? 16 : 0);
            cp_async16(smem_u32(Bs + r*SA8 + s_kc), Wt + (size_t)(bn + r)*K + k0 + s_kc, 16);
        }
        cp_commit();
    };

    issue(0);
    issue(1);

    for (int c = 0; c < nc; c++) {
        cp_wait<1>();
        __syncthreads();
        if (c + 2 < nc) issue(c + 2); else cp_commit();

        const u8* As = gsm + (c % NSTG)*STG_B;
        const u8* Bs = As + 128*SA8;
        const unsigned uA = smem_u32(As);
        const unsigned uB = smem_u32(Bs);
#pragma unroll
        for (int kk = 0; kk < 2; kk++) {
            unsigned af[4][4], bf[2][4];
#pragma unroll
            for (int i = 0; i < 4; i++) {
                unsigned addr = uA + (unsigned)((wm0 + i*16 + a_row)*SA8 + kk*32 + a_byt);
                ldsm_x4(af[i][0], af[i][1], af[i][2], af[i][3], addr);
            }
#pragma unroll
            for (int jp = 0; jp < 2; jp++) {
                unsigned addr = uB + (unsigned)((wn0 + jp*16 + b_row)*SA8 + kk*32 + b_byt);
                ldsm_x4(bf[jp][0], bf[jp][1], bf[jp][2], bf[jp][3], addr);
            }
#pragma unroll
            for (int i = 0; i < 4; i++)
#pragma unroll
                for (int j = 0; j < 4; j++)
                    mma_e4m3(acc[i][j], af[i], bf[j>>1][(j&1)*2], bf[j>>1][(j&1)*2+1]);
        }
    }

    // ---- epilogue ----
    float* Cf = (float*)Cv;
    __half* Ch = (__half*)Cv;
    u8* C8 = (u8*)Cv;
#pragma unroll
    for (int i = 0; i < 4; i++) {
#pragma unroll
        for (int hh = 0; hh < 2; hh++) {
            int row = bm + wm0 + i*16 + g + hh*8;
            if (row >= M) continue;
#pragma unroll
            for (int j = 0; j < 4; j++) {
                int col = bn + wn0 + j*8 + tg*2;
                float v0 = acc[i][j][hh*2 + 0] * IWSc;
                float v1 = acc[i][j][hh*2 + 1] * IWSc;
                if (bias) { v0 += bias[col]; v1 += bias[col+1]; }
                if (ACT == 1) { v0 = gelu_f(v0); v1 = gelu_f(v1); }
                else if (ACT == 2) { v0 = tanhf(v0); v1 = tanhf(v1); }
                if (COUT == 1) {
                    unsigned* cp = (unsigned*)(Ch + (size_t)row*N + col);
                    if (accum) {
                        float2 o = h2f(*cp);
                        v0 += o.x; v1 += o.y;
                    }
                    *cp = pack_h2(v0, v1);
                    if (C8dup) *(u16t*)(C8dup + (size_t)row*N + col) = e4m3_2(v0, v1);
                } else if (COUT == 2) {
                    *(u16t*)(C8 + (size_t)row*N + col) = e4m3_2(v0, v1);
                } else {
                    size_t ci = (size_t)row*N + col;
                    if (accum) { Cf[ci] += v0; Cf[ci+1] += v1; }
                    else       { Cf[ci]  = v0; Cf[ci+1]  = v1; }
                }
            }
        }
    }
}

// ---------------- feature attention: fp16 qkv in, fp8 out; fp16 smem tiles ----------------
__global__ __launch_bounds__(256)
void fa_attn_kernel(const __half* __restrict__ qkv, u8* __restrict__ o)
{
    __shared__ __half2 Qs[32][36], Ks[32][36], Vs[32][36];
    __shared__ float Ss[32][36];
    const int bt = blockIdx.x;
    const int h  = blockIdx.y;
    const int base = bt * 32;
    const int tid = threadIdx.x;
    for (int i = tid; i < 1024; i += 256) {
        int f = i >> 5, d2 = i & 31;
        size_t r = (size_t)(base + f)*1536 + h*64 + d2*2;
        Qs[f][d2] = *(const __half2*)(qkv + r);
        Ks[f][d2] = *(const __half2*)(qkv + r + 512);
        Vs[f][d2] = *(const __half2*)(qkv + r + 1024);
    }
    __syncthreads();
    for (int i = tid; i < 1024; i += 256) {
        int qi = i >> 5, ki = i & 31;
        const uint4* qp = (const uint4*)Qs[qi];
        const uint4* kp = (const uint4*)Ks[ki];
        float s = 0.f;
#pragma unroll
        for (int j = 0; j < 8; j++) {
            uint4 a = qp[j], b = kp[j];
            float2 a0 = h2f(a.x), a1 = h2f(a.y), a2 = h2f(a.z), a3 = h2f(a.w);
            float2 b0 = h2f(b.x), b1 = h2f(b.y), b2 = h2f(b.z), b3 = h2f(b.w);
            s += a0.x*b0.x + a0.y*b0.y + a1.x*b1.x + a1.y*b1.y
               + a2.x*b2.x + a2.y*b2.y + a3.x*b3.x + a3.y*b3.y;
        }
        Ss[qi][ki] = s * 0.125f;
    }
    __syncthreads();
    const int w = tid >> 5, lane = tid & 31;
    for (int qi = w; qi < 32; qi += 8) {
        float v = Ss[qi][lane];
        float m = v;
#pragma unroll
        for (int oo = 16; oo > 0; oo >>= 1) m = fmaxf(m, __shfl_xor_sync(0xffffffffu, m, oo));
        float e  = expf(v - m);
        float su = e;
#pragma unroll
        for (int oo = 16; oo > 0; oo >>= 1) su += __shfl_xor_sync(0xffffffffu, su, oo);
        Ss[qi][lane] = e / su;
    }
    __syncthreads();
    for (int i = tid; i < 1024; i += 256) {
        int f = i >> 5, d2 = i & 31;
        const float4* sp = (const float4*)Ss[f];
        float a0 = 0.f, a1 = 0.f;
#pragma unroll
        for (int k4 = 0; k4 < 8; k4++) {
            float4 sv = sp[k4];
            float2 v0 = __half22float2(Vs[k4*4+0][d2]);
            float2 v1 = __half22float2(Vs[k4*4+1][d2]);
            float2 v2 = __half22float2(Vs[k4*4+2][d2]);
            float2 v3 = __half22float2(Vs[k4*4+3][d2]);
            a0 += sv.x*v0.x + sv.y*v1.x + sv.z*v2.x + sv.w*v3.x;
            a1 += sv.x*v0.y + sv.y*v1.y + sv.z*v2.y + sv.w*v3.y;
        }
        *(u16t*)(o + (size_t)(base + f)*512 + h*64 + d2*2) = e4m3_2(a0, a1);
    }
}

// ---------------- horse attention: fp16 qkv in, fp8 out, key-masked; fp16 smem ----------------
__global__ __launch_bounds__(128)
void ha_attn_kernel(const __half* __restrict__ qkv, u8* __restrict__ o,
                    const float* __restrict__ amask)
{
    __shared__ __half2 Qs[16][36], Ks[16][36], Vs[16][36];
    __shared__ float Ss[16][20];
    const int bf = blockIdx.x;
    const int h  = blockIdx.y;
    const int b  = bf >> 5, f = bf & 31;
    const int tid = threadIdx.x;
    for (int i = tid; i < 512; i += 128) {
        int t = i >> 5, d2 = i & 31;
        size_t r = (size_t)((b*16 + t)*32 + f)*1536 + h*64 + d2*2;
        Qs[t][d2] = *(const __half2*)(qkv + r);
        Ks[t][d2] = *(const __half2*)(qkv + r + 512);
        Vs[t][d2] = *(const __half2*)(qkv + r + 1024);
    }
    __syncthreads();
    for (int i = tid; i < 256; i += 128) {
        int qi = i >> 4, ki = i & 15;
        const uint4* qp = (const uint4*)Qs[qi];
        const uint4* kp = (const uint4*)Ks[ki];
        float s = 0.f;
#pragma unroll
        for (int j = 0; j < 8; j++) {
            uint4 a = qp[j], bb = kp[j];
            float2 a0 = h2f(a.x), a1 = h2f(a.y), a2 = h2f(a.z), a3 = h2f(a.w);
            float2 b0 = h2f(bb.x), b1 = h2f(bb.y), b2 = h2f(bb.z), b3 = h2f(bb.w);
            s += a0.x*b0.x + a0.y*b0.y + a1.x*b1.x + a1.y*b1.y
               + a2.x*b2.x + a2.y*b2.y + a3.x*b3.x + a3.y*b3.y;
        }
        s *= 0.125f;
        float mk = (ki < 15) ? amask[b*15 + ki] : 1.f;
        Ss[qi][ki] = (mk > 0.f) ? s : -1e9f;
    }
    __syncthreads();
    if (tid < 16) {
        float m = -1e30f;
#pragma unroll
        for (int k = 0; k < 16; k++) m = fmaxf(m, Ss[tid][k]);
        float su = 0.f;
#pragma unroll
        for (int k = 0; k < 16; k++) { float e = expf(Ss[tid][k] - m); Ss[tid][k] = e; su += e; }
        float inv = 1.f / su;
#pragma unroll
        for (int k = 0; k < 16; k++) Ss[tid][k] *= inv;
    }
    __syncthreads();
    for (int i = tid; i < 512; i += 128) {
        int t = i >> 5, d2 = i & 31;
        const float4* sp = (const float4*)Ss[t];
        float a0 = 0.f, a1 = 0.f;
#pragma unroll
        for (int k4 = 0; k4 < 4; k4++) {
            float4 sv = sp[k4];
            float2 v0 = __half22float2(Vs[k4*4+0][d2]);
            float2 v1 = __half22float2(Vs[k4*4+1][d2]);
            float2 v2 = __half22float2(Vs[k4*4+2][d2]);
            float2 v3 = __half22float2(Vs[k4*4+3][d2]);
            a0 += sv.x*v0.x + sv.y*v1.x + sv.z*v2.x + sv.w*v3.x;
            a1 += sv.x*v0.y + sv.y*v1.y + sv.z*v2.y + sv.w*v3.y;
        }
        *(u16t*)(o + (size_t)((b*16 + t)*32 + f)*512 + h*64 + d2*2) = e4m3_2(a0, a1);
    }
}

// ---------------- pooling ----------------
__global__ __launch_bounds__(128)
void rowdot_kernel(const __half* __restrict__ T, const float* __restrict__ v,
                   float* __restrict__ out)
{
    int row = blockIdx.x, tid = threadIdx.x;
    const __half2* tr = (const __half2*)(T + (size_t)row*Dd);
    float2 a0 = __half22float2(tr[tid*2]);
    float2 a1 = __half22float2(tr[tid*2+1]);
    float4 w = ((const float4*)v)[tid];
    float s = a0.x*w.x + a0.y*w.y + a1.x*w.z + a1.y*w.w;
    s = warp_sum(s);
    __shared__ float red[4];
    if ((tid & 31) == 0) red[tid >> 5] = s;
    __syncthreads();
    if (tid == 0) out[row] = red[0]+red[1]+red[2]+red[3];
}

__global__ __launch_bounds__(256)
void pool_kernel(const float* __restrict__ s, const __half* __restrict__ seq,
                 float* __restrict__ pooled)
{
    int bt = blockIdx.x;
    int tid = threadIdx.x;
    __shared__ float aw[32];
    if (tid < 32) {
        float v = s[bt*32 + tid];
        float m = v;
#pragma unroll
        for (int o = 16; o > 0; o >>= 1) m = fmaxf(m, __shfl_xor_sync(0xffffffffu, m, o));
        float e  = expf(v - m);
        float su = e;
#pragma unroll
        for (int o = 16; o > 0; o >>= 1) su += __shfl_xor_sync(0xffffffffu, su, o);
        aw[tid] = e / su;
    }
    __syncthreads();
    int d2 = tid;
    float ax = 0.f, ay = 0.f;
#pragma unroll
    for (int f = 0; f < 32; f++) {
        float2 xf = __half22float2(*(const __half2*)(seq + ((size_t)bt*32 + f)*Dd + d2*2));
        ax += aw[f]*xf.x; ay += aw[f]*xf.y;
    }
    pooled[(size_t)bt*Dd + d2*2]     = ax;
    pooled[(size_t)bt*Dd + d2*2 + 1] = ay;
}

__global__ __launch_bounds__(256)
void combine_kernel(const float* __restrict__ pooled, u8* __restrict__ comb)
{
    int idx = blockIdx.x*256 + threadIdx.x;
    int bh = idx >> 9;
    int c  = (idx & 511) * 2;
    int b = bh / 15, h = bh % 15;
    float2 p;
    if (c < 512) p = *(const float2*)(pooled + (b*16 + h)*Dd + c);
    else         p = *(const float2*)(pooled + (b*16 + 15)*Dd + (c - 512));
    ((u16t*)comb)[idx] = e4m3_2(p.x, p.y);
}

__global__ __launch_bounds__(256)
void maskmul_kernel(const float* __restrict__ feat, const float* __restrict__ amask,
                    u8* __restrict__ feat8)
{
    int idx = blockIdx.x*256 + threadIdx.x;
    float2 p = *(const float2*)(feat + idx*2);
    float mk = amask[idx >> 8];
    ((u16t*)feat8)[idx] = e4m3_2(p.x*mk, p.y*mk);
}

// ---------------- MCMC ----------------
__global__ __launch_bounds__(512)
void mcmc_kernel(const float* __restrict__ U, const float* __restrict__ e_w1,
                 const float* __restrict__ e_w2, const float* __restrict__ amask,
                 const float* __restrict__ pred0, const int* __restrict__ nsteps,
                 float* __restrict__ out)
{
    const int bh = blockIdx.x;
    const int b  = bh / 15;
    const int j  = threadIdx.x;
    const float u  = U[(size_t)bh*Dd + j];
    const float wj = e_w1[512*512 + j];
    const float wc = wj * e_w2[j];
    const float mk = amask[bh];
    __shared__ float red[16];
    __shared__ float sp, shpr;
    if (j == 0) {
        float s = 0.f;
        for (int i = 0; i < 15; i++) s += amask[b*15 + i];
        shpr = s;
        sp = pred0[bh];
    }
    __syncthreads();
    const int n = *nsteps;
    for (int st = 0; st < n; st++) {
        float p = sp;
        float a = u + p*wj;
        float v = gelu_grad(a) * wc;
        v = warp_sum(v);
        if ((j & 31) == 0) red[j >> 5] = v;
        __syncthreads();
        if (j == 0) {
            float de = 0.f;
#pragma unroll
            for (int w = 0; w < 16; w++) de += red[w];
            float dent = -( logf(p + EPSc) + p/(p + EPSc)
                          - logf(1.f - p + EPSc) - (1.f - p)/(1.f - p + EPSc) );
            float g = (mk/(shpr*64.f)) * (de - 0.05f*dent);
            p = p - 0.1f*g*mk;
            p = (tanhf(p - 0.5f) + 1.f)*0.5f*(1.f - 2e-7f) + 1e-7f;
            p = fminf(fmaxf(p, EPSc), 1.f - EPSc);
            sp = p;
        }
        __syncthreads();
    }
    if (j == 0) out[bh] = sp;
}

// ---------------- host launch ----------------
static void launch_qgemm(int act, int cout, const u8* A, const u8* Wt, void* C,
                         int M, int N, int K, const float* bias, int accum, u8* c8dup)
{
    dim3 grid(N/128, (M + 127)/128);
    if (cout == 1) {
        if (act == 0) {
            cudaFuncSetAttribute(qgemm_kernel<0,1>, cudaFuncAttributeMaxDynamicSharedMemorySize, GSM_B);
            qgemm_kernel<0,1><<<grid, 256, GSM_B>>>(A, Wt, C, M, N, K, bias, accum, c8dup);
        } else if (act == 2) {
            cudaFuncSetAttribute(qgemm_kernel<2,1>, cudaFuncAttributeMaxDynamicSharedMemorySize, GSM_B);
            qgemm_kernel<2,1><<<grid, 256, GSM_B>>>(A, Wt, C, M, N, K, bias, accum, c8dup);
        } else {
            cudaFuncSetAttribute(qgemm_kernel<1,1>, cudaFuncAttributeMaxDynamicSharedMemorySize, GSM_B);
            qgemm_kernel<1,1><<<grid, 256, GSM_B>>>(A, Wt, C, M, N, K, bias, accum, c8dup);
        }
    } else if (cout == 2) {
        cudaFuncSetAttribute(qgemm_kernel<1,2>, cudaFuncAttributeMaxDynamicSharedMemorySize, GSM_B);
        qgemm_kernel<1,2><<<grid, 256, GSM_B>>>(A, Wt, C, M, N, K, bias, accum, nullptr);
    } else {
        cudaFuncSetAttribute(qgemm_kernel<0,0>, cudaFuncAttributeMaxDynamicSharedMemorySize, GSM_B);
        qgemm_kernel<0,0><<<grid, 256, GSM_B>>>(A, Wt, C, M, N, K, bias, accum, nullptr);
    }
}
static void launch_wcvt2(const float* in0, u8* out0, const float* in1, u8* out1,
                         int K, int N, int L0, int L1)
{
    dim3 grid(N/32, K/32, L0 + L1);
    wcvt_kernel<<<grid, 256>>>(in0, out0, in1, out1, K, N, L0);
}

extern "C" void kernel_launch(void* const* d_in, const int* in_sizes, int n_in,
                              void* d_out, int out_size)
{
    const float* x_cont  = (const float*)d_in[0];
    const int*   x_cat   = (const int*)  d_in[1];
    const float* amask   = (const float*)d_in[2];
    const float* pred0   = (const float*)d_in[3];
    const float* emb_w   = (const float*)d_in[4];
    const float* emb_b   = (const float*)d_in[5];
    const float* cat_emb = (const float*)d_in[6];
    const float* cls     = (const float*)d_in[7];
    const float* fa_wqkv = (const float*)d_in[8];
    const float* fa_wo   = (const float*)d_in[9];
    const float* ha_wqkv = (const float*)d_in[10];
    const float* ha_wo   = (const float*)d_in[11];
    const float* ffn_w1  = (const float*)d_in[12];
    const float* ffn_b1  = (const float*)d_in[13];
    const float* ffn_w2  = (const float*)d_in[14];
    const float* ffn_b2  = (const float*)d_in[15];
    const float* ln1_g   = (const float*)d_in[16];
    const float* ln1_b   = (const float*)d_in[17];
    const float* ln2_g   = (const float*)d_in[18];
    const float* ln2_b   = (const float*)d_in[19];
    const float* ln3_g   = (const float*)d_in[20];
    const float* ln3_b   = (const float*)d_in[21];
    const float* pool_w  = (const float*)d_in[22];
    const float* pool_b  = (const float*)d_in[23];
    const float* pool_v  = (const float*)d_in[24];
    const float* proj_w  = (const float*)d_in[25];
    const float* proj_b  = (const float*)d_in[26];
    const float* e_w1    = (const float*)d_in[27];
    const float* e_b1    = (const float*)d_in[28];
    const float* e_w2    = (const float*)d_in[29];
    const int*   nsteps  = (const int*)  d_in[31];
    float* out = (float*)d_out;

    float *sbuf, *pool, *feat, *ubuf;
    __half *seqh, *qkvh;
    u8 *a8, *f8, *w8, *comb8, *feat8;
    cudaGetSymbolAddress((void**)&seqh, g_seqh);
    cudaGetSymbolAddress((void**)&qkvh, g_qkvh);
    cudaGetSymbolAddress((void**)&a8,   g_a8);
    cudaGetSymbolAddress((void**)&f8,   g_f8);
    cudaGetSymbolAddress((void**)&w8,   g_w8);
    cudaGetSymbolAddress((void**)&sbuf, g_s);
    cudaGetSymbolAddress((void**)&pool, g_pool);
    cudaGetSymbolAddress((void**)&comb8,g_comb8);
    cudaGetSymbolAddress((void**)&feat, g_feat);
    cudaGetSymbolAddress((void**)&feat8,g_feat8);
    cudaGetSymbolAddress((void**)&ubuf, g_u);

    // launch order: #4 is the hot QKV GEMM (for ncu -s capture)
    embed_kernel<<<(NTOK*Dd/2)/256, 256>>>(x_cont, x_cat, emb_w, emb_b, cat_emb, cls, seqh);
    ln2_kernel<<<NTOK/8, 256>>>(seqh, a8, ln1_g, ln1_b);
    launch_wcvt2(fa_wqkv, w8 + OFF_FAQKV, ha_wqkv, w8 + OFF_HAQKV, 512, 1536, 4, 4);
    launch_qgemm(0, 1, a8, w8 + OFF_FAQKV, qkvh, NTOK, 3*Dd, Dd, nullptr, 0, nullptr);

    // deferred weight conversions
    launch_wcvt2(fa_wo,  w8 + OFF_FAWO, ha_wo, w8 + OFF_HAWO, 512, 512, 4, 4);
    launch_wcvt2(ffn_w1, w8 + OFF_FFN1, ffn_w1, w8 + OFF_FFN1, 512, 2048, 4, 0);
    launch_wcvt2(ffn_w2, w8 + OFF_FFN2, ffn_w2, w8 + OFF_FFN2, 2048, 512, 4, 0);
    launch_wcvt2(pool_w, w8 + OFF_POOLW, e_w1, w8 + OFF_EW1,   512, 512,  1, 1);
    launch_wcvt2(proj_w, w8 + OFF_PROJW, proj_w, w8 + OFF_PROJW, 1024, 512, 1, 0);

    for (int l = 0; l < Ll; l++) {
        if (l > 0) {
            ln2_kernel<<<NTOK/8, 256>>>(seqh, a8, ln1_g + l*Dd, ln1_b + l*Dd);
            launch_qgemm(0, 1, a8, w8 + OFF_FAQKV + (size_t)l*512*1536, qkvh, NTOK, 3*Dd, Dd, nullptr, 0, nullptr);
        }
        fa_attn_kernel<<<dim3(Bb*Tt, NHh), 256>>>(qkvh, a8);
        launch_qgemm(0, 1, a8, w8 + OFF_FAWO + (size_t)l*512*512, seqh, NTOK, Dd, Dd, nullptr, 1, nullptr);

        ln2_kernel<<<NTOK/8, 256>>>(seqh, a8, ln2_g + l*Dd, ln2_b + l*Dd);
        launch_qgemm(0, 1, a8, w8 + OFF_HAQKV + (size_t)l*512*1536, qkvh, NTOK, 3*Dd, Dd, nullptr, 0, nullptr);
        ha_attn_kernel<<<dim3(Bb*Ff, NHh), 128>>>(qkvh, a8, amask);
        launch_qgemm(0, 1, a8, w8 + OFF_HAWO + (size_t)l*512*512, seqh, NTOK, Dd, Dd, nullptr, 1, nullptr);

        ln2_kernel<<<NTOK/8, 256>>>(seqh, a8, ln3_g + l*Dd, ln3_b + l*Dd);
        launch_qgemm(1, 2, a8, w8 + OFF_FFN1 + (size_t)l*512*2048, f8, NTOK, DFFf, Dd, ffn_b1 + l*DFFf, 0, nullptr);
        launch_qgemm(0, 1, f8, w8 + OFF_FFN2 + (size_t)l*512*2048, seqh, NTOK, Dd, DFFf, ffn_b2 + l*Dd, 1,
                     (l == Ll-1) ? a8 : nullptr);
    }

    // attention pooling
    launch_qgemm(2, 1, a8, w8 + OFF_POOLW, qkvh, NTOK, Dd, Dd, pool_b, 0, nullptr);
    rowdot_kernel<<<NTOK, 128>>>(qkvh, pool_v, sbuf);
    pool_kernel<<<Bb*Tt, 256>>>(sbuf, seqh, pool);
    combine_kernel<<<(Bb*Hh*512)/256, 256>>>(pool, comb8);
    launch_qgemm(0, 0, comb8, w8 + OFF_PROJW, feat, Bb*Hh, Dd, 2*Dd, proj_b, 0, nullptr);
    maskmul_kernel<<<(Bb*Hh*256)/256, 256>>>(feat, amask, feat8);

    // energy precompute
    launch_qgemm(0, 0, feat8, w8 + OFF_EW1, ubuf, Bb*Hh, Dd, Dd, e_b1, 0, nullptr);

    // MCMC
    mcmc_kernel<<<Bb*Hh, 512>>>(ubuf, e_w1, e_w2, amask, pred0, nsteps, out);
}

// round 17
// speedup vs baseline: 1.0368x; 1.0368x over previous
#include <cuda_runtime.h>
#include <cuda_fp16.h>
#include <math.h>

typedef unsigned char u8;
typedef unsigned short u16t;

// ---------------- problem constants ----------------
#define Bb   64
#define Hh   15
#define Tt   16
#define Ff   32
#define Dd   512
#define NHh  8
#define Ll   4
#define DFFf 2048
#define NTOK (Bb*Tt*Ff)          // 32768 rows
#define EPSc 1e-7f
#define WSc   16.0f              // fp8 weight scale
#define IWSc  0.0625f

// fp8 transposed-weight pool offsets (bytes); each weight stored [N,K]
#define OFF_FAQKV 0
#define SZ_FAQKV  (4*512*1536)
#define OFF_FAWO  (OFF_FAQKV + SZ_FAQKV)
#define SZ_FAWO   (4*512*512)
#define OFF_HAQKV (OFF_FAWO + SZ_FAWO)
#define OFF_HAWO  (OFF_HAQKV + SZ_FAQKV)
#define OFF_FFN1  (OFF_HAWO + SZ_FAWO)
#define SZ_FFN1   (4*512*2048)
#define OFF_FFN2  (OFF_FFN1 + SZ_FFN1)
#define OFF_POOLW (OFF_FFN2 + SZ_FFN1)
#define SZ_POOLW  (512*512)
#define OFF_PROJW (OFF_POOLW + SZ_POOLW)
#define SZ_PROJW  (1024*512)
#define OFF_EW1   (OFF_PROJW + SZ_PROJW)
#define SZ_EW1    (512*512)
#define W8_TOTAL  (OFF_EW1 + SZ_EW1)

// GEMM smem — 3-stage
#define SA8 80                               // smem row stride (bytes)
#define STG_B (2*128*SA8)                    // A+B per stage = 20480 B
#define NSTG 3
#define GSM_B (NSTG*STG_B)                   // 61440 B dynamic smem

// ---------------- scratch (device globals) ----------------
__device__ __half g_seqh[NTOK*Dd];
__device__ __half g_qkvh[NTOK*3*Dd];         // fp16 qkv / pool tanh buf
__device__ u8     g_a8 [NTOK*Dd];
__device__ u8     g_f8 [NTOK*DFFf];
__device__ u8     g_w8 [W8_TOTAL];
__device__ float  g_s  [NTOK];
__device__ float  g_pool[Bb*Tt*Dd];
__device__ u8     g_comb8[Bb*Hh*2*Dd];
__device__ float  g_feat[Bb*Hh*Dd];
__device__ u8     g_feat8[Bb*Hh*Dd];
__device__ float  g_u  [Bb*Hh*Dd];

// ---------------- helpers ----------------
__device__ __forceinline__ float warp_sum(float v){
#pragma unroll
    for (int o = 16; o > 0; o >>= 1) v += __shfl_xor_sync(0xffffffffu, v, o);
    return v;
}
__device__ __forceinline__ float gelu_f(float x){
    float x3 = x*x*x;
    float t  = tanhf(0.7978845608028654f*(x + 0.044715f*x3));
    return 0.5f*x*(1.f + t);
}
__device__ __forceinline__ float gelu_grad(float x){
    float x2 = x*x;
    float t  = tanhf(0.7978845608028654f*(x + 0.044715f*x2*x));
    float sech2 = 1.f - t*t;
    return 0.5f*(1.f + t) + 0.5f*x*sech2*0.7978845608028654f*(1.f + 3.f*0.044715f*x2);
}
__device__ __forceinline__ unsigned smem_u32(const void* p){
    return (unsigned)__cvta_generic_to_shared(p);
}
__device__ __forceinline__ unsigned pack_h2(float a, float b){
    unsigned lo = (unsigned)__half_as_ushort(__float2half_rn(a));
    unsigned hi = (unsigned)__half_as_ushort(__float2half_rn(b));
    return lo | (hi << 16);
}
__device__ __forceinline__ u16t e4m3_2(float lo, float hi){
    u16t r;
    asm("cvt.rn.satfinite.e4m3x2.f32 %0, %1, %2;" : "=h"(r) : "f"(hi), "f"(lo));
    return r;
}
__device__ __forceinline__ float2 h2f(unsigned h){
    return __half22float2(*(__half2*)&h);
}
__device__ __forceinline__ void ldsm_x4(unsigned& r0, unsigned& r1, unsigned& r2, unsigned& r3, unsigned a){
    asm volatile("ldmatrix.sync.aligned.m8n8.x4.shared.b16 {%0,%1,%2,%3},[%4];\n"
        : "=r"(r0), "=r"(r1), "=r"(r2), "=r"(r3) : "r"(a));
}
__device__ __forceinline__ void mma_e4m3(float* c, const unsigned* a, unsigned b0, unsigned b1){
    asm volatile("mma.sync.aligned.m16n8k32.row.col.f32.e4m3.e4m3.f32 "
        "{%0,%1,%2,%3}, {%4,%5,%6,%7}, {%8,%9}, {%0,%1,%2,%3};\n"
        : "+f"(c[0]), "+f"(c[1]), "+f"(c[2]), "+f"(c[3])
        : "r"(a[0]), "r"(a[1]), "r"(a[2]), "r"(a[3]), "r"(b0), "r"(b1));
}
__device__ __forceinline__ void cp_async16(unsigned dst, const void* src, int srcsize){
    asm volatile("cp.async.cg.shared.global [%0], [%1], 16, %2;\n" :: "r"(dst), "l"(src), "r"(srcsize));
}
__device__ __forceinline__ void cp_commit(){ asm volatile("cp.async.commit_group;\n"); }
template<int N> __device__ __forceinline__ void cp_wait(){
    asm volatile("cp.async.wait_group %0;\n" :: "n"(N));
}

// ---------------- weight transpose+convert: [K,N] f32 -> [N,K] fp8 x16 ----------------
__global__ __launch_bounds__(256)
void wcvt_kernel(const float* __restrict__ in0, u8* __restrict__ out0,
                 const float* __restrict__ in1, u8* __restrict__ out1,
                 int K, int N, int L0)
{
    __shared__ float t[32][33];
    int z = blockIdx.z;
    const float* inz;
    u8* outz;
    if (z < L0) { inz = in0 + (size_t)z * K * N;        outz = out0 + (size_t)z * K * N; }
    else        { inz = in1 + (size_t)(z - L0) * K * N; outz = out1 + (size_t)(z - L0) * K * N; }
    int kb = blockIdx.y*32, nb = blockIdx.x*32;
    int tx = threadIdx.x & 31, ty = threadIdx.x >> 5;
#pragma unroll
    for (int j = 0; j < 32; j += 8)
        t[ty+j][tx] = inz[(size_t)(kb+ty+j)*N + nb+tx];
    __syncthreads();
#pragma unroll
    for (int j = 0; j < 32; j += 8) {
        float v = t[tx][ty+j] * WSc;
        u16t p = e4m3_2(v, 0.f);
        outz[(size_t)(nb+ty+j)*K + kb+tx] = (u8)(p & 0xff);
    }
}

// ---------------- embedding -> fp16 seq ----------------
__global__ __launch_bounds__(256)
void embed_kernel(const float* __restrict__ x_cont, const int* __restrict__ x_cat,
                  const float* __restrict__ emb_w, const float* __restrict__ emb_b,
                  const float* __restrict__ cat_emb, const float* __restrict__ cls,
                  __half* __restrict__ seq)
{
    int idx = blockIdx.x*256 + threadIdx.x;
    int d  = (idx & 255) * 2;
    int f  = (idx >> 8)  & 31;
    int t  = (idx >> 13) & 15;
    int b  =  idx >> 17;
    float v0, v1;
    if (t == Tt-1) {
        float2 c = *(const float2*)(cls + f*Dd + d);
        v0 = c.x; v1 = c.y;
    } else if (f < 24) {
        float xc = x_cont[(b*Hh + t)*24 + f];
        float2 w = *(const float2*)(emb_w + f*Dd + d);
        float2 e = *(const float2*)(emb_b + f*Dd + d);
        v0 = xc*w.x + e.x; v1 = xc*w.y + e.y;
    } else {
        int fc = f - 24;
        int c  = x_cat[(b*Hh + t)*8 + fc];
        float2 e = *(const float2*)(cat_emb + ((size_t)fc*50 + c)*Dd + d);
        v0 = e.x; v1 = e.y;
    }
    ((unsigned*)seq)[idx] = pack_h2(v0, v1);
}

// ---------------- layernorm: warp per row, g/b cached in smem, fp16 in, fp8 out ----------------
__global__ __launch_bounds__(256)
void ln2_kernel(const __half* __restrict__ X, u8* __restrict__ Y,
                const float* __restrict__ gg, const float* __restrict__ bb)
{
    __shared__ float sg[Dd], sb[Dd];
    const int tid  = threadIdx.x;
    if (tid < 128) {
        ((float4*)sg)[tid] = ((const float4*)gg)[tid];
    } else {
        ((float4*)sb)[tid - 128] = ((const float4*)bb)[tid - 128];
    }
    __syncthreads();

    const int row  = blockIdx.x*8 + (tid >> 5);
    const int lane = tid & 31;
    const uint4* xr = (const uint4*)(X + (size_t)row*Dd);
    float x[16];
    float s = 0.f, s2 = 0.f;
#pragma unroll
    for (int j = 0; j < 2; j++) {
        uint4 u = xr[lane + 32*j];
        float2 p0 = h2f(u.x), p1 = h2f(u.y), p2 = h2f(u.z), p3 = h2f(u.w);
        x[j*8+0]=p0.x; x[j*8+1]=p0.y; x[j*8+2]=p1.x; x[j*8+3]=p1.y;
        x[j*8+4]=p2.x; x[j*8+5]=p2.y; x[j*8+6]=p3.x; x[j*8+7]=p3.y;
    }
#pragma unroll
    for (int i = 0; i < 16; i++) { s += x[i]; s2 += x[i]*x[i]; }
#pragma unroll
    for (int o = 16; o > 0; o >>= 1) {
        s  += __shfl_xor_sync(0xffffffffu, s,  o);
        s2 += __shfl_xor_sync(0xffffffffu, s2, o);
    }
    float mean = s * (1.f/Dd);
    float var  = s2 * (1.f/Dd) - mean*mean;
    float inv  = rsqrtf(var + 1e-5f);
#pragma unroll
    for (int j = 0; j < 2; j++) {
        int base = (lane + 32*j)*8;
        u16t h[4];
#pragma unroll
        for (int q = 0; q < 4; q++) {
            h[q] = e4m3_2((x[j*8+q*2  ]-mean)*inv*sg[base+q*2  ] + sb[base+q*2  ],
                          (x[j*8+q*2+1]-mean)*inv*sg[base+q*2+1] + sb[base+q*2+1]);
        }
        uint2 o;
        o.x = (unsigned)h[0] | ((unsigned)h[1] << 16);
        o.y = (unsigned)h[2] | ((unsigned)h[3] << 16);
        *(uint2*)(Y + (size_t)row*Dd + base) = o;
    }
}

// ---------------- fp8 tensor-core GEMM: 128 thr, 4 warps, warp 64x64, hoisted addrs ----------------
// C[M,N] (+)= act(A[M,K] @ Wt[N,K]^T * 1/16 + bias); A,Wt e4m3.
// Block 128x128x64, 4 warps (2m x 2n), mma m16n8k32, 3-stage cp.async.
// All 16 ldsm issued before the 32 mma (two fragment sets) for back-to-back mma issue.
// Requires N % 128 == 0, K % 64 == 0, K >= 192.
template<int ACT, int COUT>   // ACT: 0 none, 1 gelu, 2 tanh; COUT: 0 f32, 1 f16, 2 fp8
__global__ __launch_bounds__(128, 2)
void qgemm_kernel(const u8* __restrict__ A, const u8* __restrict__ Wt,
                  void* __restrict__ Cv, int M, int N, int K,
                  const float* __restrict__ bias, int accum, u8* __restrict__ C8dup)
{
    extern __shared__ __align__(16) u8 gsm[];
    const int tid  = threadIdx.x;
    const int lane = tid & 31;
    const int warp = tid >> 5;
    const int wm0  = (warp & 1) * 64;
    const int wn0  = (warp >> 1) * 64;
    const int bm   = blockIdx.y * 128;
    const int bn   = blockIdx.x * 128;
    const int g    = lane >> 2;
    const int tg   = lane & 3;

    const int s_r0 = tid >> 2;
    const int s_kc = (tid & 3) * 16;

    const int a_row = lane & 15;
    const int a_byt = (lane >> 4) * 16;
    const int b_row = ((lane >> 4) & 1) * 8 + (lane & 7);
    const int b_byt = ((lane >> 3) & 1) * 16;

    float acc[4][8][4];
#pragma unroll
    for (int i = 0; i < 4; i++)
#pragma unroll
        for (int j = 0; j < 8; j++)
#pragma unroll
            for (int q = 0; q < 4; q++) acc[i][j][q] = 0.f;

    const int nc = K >> 6;
    const unsigned u0 = smem_u32(gsm);

    // hoisted ldsm base addresses (stage 0, kk 0)
    unsigned adA[4], adB[4];
#pragma unroll
    for (int i = 0; i < 4; i++)
        adA[i] = u0 + (unsigned)((wm0 + i*16 + a_row)*SA8 + a_byt);
#pragma unroll
    for (int jp = 0; jp < 4; jp++)
        adB[jp] = u0 + (unsigned)(128*SA8 + (wn0 + jp*16 + b_row)*SA8 + b_byt);

    auto issue = [&](int c){
        u8* As = gsm + (c % NSTG)*STG_B;
        u8* Bs = As + 128*SA8;
        int k0 = c << 6;
#pragma unroll
        for (int it = 0; it < 4; it++) {
            int r = s_r0 + it*32;
            int gr = bm + r;
            cp_async16(smem_u32(As + r*SA8 + s_kc), A + (size_t)gr*K + k0 + s_kc,
                       gr < M ? 16 : 0);
            cp_async16(smem_u32(Bs + r*SA8 + s_kc), Wt + (size_t)(bn + r)*K + k0 + s_kc, 16);
        }
        cp_commit();
    };

    issue(0);
    issue(1);

    for (int c = 0; c < nc; c++) {
        cp_wait<1>();
        __syncthreads();
        if (c + 2 < nc) issue(c + 2); else cp_commit();

        // ---- all 16 ldsm first (two kk fragment sets), then 32 back-to-back mma ----
        unsigned af0[4][4], bf0[4][4], af1[4][4], bf1[4][4];
#pragma unroll
        for (int i = 0; i < 4; i++)
            ldsm_x4(af0[i][0], af0[i][1], af0[i][2], af0[i][3], adA[i]);
#pragma unroll
        for (int jp = 0; jp < 4; jp++)
            ldsm_x4(bf0[jp][0], bf0[jp][1], bf0[jp][2], bf0[jp][3], adB[jp]);
#pragma unroll
        for (int i = 0; i < 4; i++)
            ldsm_x4(af1[i][0], af1[i][1], af1[i][2], af1[i][3], adA[i] + 32);
#pragma unroll
        for (int jp = 0; jp < 4; jp++)
            ldsm_x4(bf1[jp][0], bf1[jp][1], bf1[jp][2], bf1[jp][3], adB[jp] + 32);

#pragma unroll
        for (int i = 0; i < 4; i++)
#pragma unroll
            for (int j = 0; j < 8; j++)
                mma_e4m3(acc[i][j], af0[i], bf0[j>>1][(j&1)*2], bf0[j>>1][(j&1)*2+1]);
#pragma unroll
        for (int i = 0; i < 4; i++)
#pragma unroll
            for (int j = 0; j < 8; j++)
                mma_e4m3(acc[i][j], af1[i], bf1[j>>1][(j&1)*2], bf1[j>>1][(j&1)*2+1]);

        // advance hoisted addresses to next stage
        unsigned d = (c % NSTG == NSTG-1) ? (unsigned)(-(NSTG-1)*STG_B) : (unsigned)STG_B;
#pragma unroll
        for (int i = 0; i < 4; i++) { adA[i] += d; adB[i] += d; }
    }

    // ---- epilogue ----
    float* Cf = (float*)Cv;
    __half* Ch = (__half*)Cv;
    u8* C8 = (u8*)Cv;
#pragma unroll
    for (int i = 0; i < 4; i++) {
#pragma unroll
        for (int hh = 0; hh < 2; hh++) {
            int row = bm + wm0 + i*16 + g + hh*8;
            if (row >= M) continue;
#pragma unroll
            for (int j = 0; j < 8; j++) {
                int col = bn + wn0 + j*8 + tg*2;
                float v0 = acc[i][j][hh*2 + 0] * IWSc;
                float v1 = acc[i][j][hh*2 + 1] * IWSc;
                if (bias) { v0 += bias[col]; v1 += bias[col+1]; }
                if (ACT == 1) { v0 = gelu_f(v0); v1 = gelu_f(v1); }
                else if (ACT == 2) { v0 = tanhf(v0); v1 = tanhf(v1); }
                if (COUT == 1) {
                    unsigned* cp = (unsigned*)(Ch + (size_t)row*N + col);
                    if (accum) {
                        float2 o = h2f(*cp);
                        v0 += o.x; v1 += o.y;
                    }
                    *cp = pack_h2(v0, v1);
                    if (C8dup) *(u16t*)(C8dup + (size_t)row*N + col) = e4m3_2(v0, v1);
                } else if (COUT == 2) {
                    *(u16t*)(C8 + (size_t)row*N + col) = e4m3_2(v0, v1);
                } else {
                    size_t ci = (size_t)row*N + col;
                    if (accum) { Cf[ci] += v0; Cf[ci+1] += v1; }
                    else       { Cf[ci]  = v0; Cf[ci+1]  = v1; }
                }
            }
        }
    }
}

// ---------------- feature attention: fp16 qkv in, fp8 out; fp16 smem tiles ----------------
__global__ __launch_bounds__(256)
void fa_attn_kernel(const __half* __restrict__ qkv, u8* __restrict__ o)
{
    __shared__ __half2 Qs[32][36], Ks[32][36], Vs[32][36];
    __shared__ float Ss[32][36];
    const int bt = blockIdx.x;
    const int h  = blockIdx.y;
    const int base = bt * 32;
    const int tid = threadIdx.x;
    for (int i = tid; i < 1024; i += 256) {
        int f = i >> 5, d2 = i & 31;
        size_t r = (size_t)(base + f)*1536 + h*64 + d2*2;
        Qs[f][d2] = *(const __half2*)(qkv + r);
        Ks[f][d2] = *(const __half2*)(qkv + r + 512);
        Vs[f][d2] = *(const __half2*)(qkv + r + 1024);
    }
    __syncthreads();
    for (int i = tid; i < 1024; i += 256) {
        int qi = i >> 5, ki = i & 31;
        const uint4* qp = (const uint4*)Qs[qi];
        const uint4* kp = (const uint4*)Ks[ki];
        float s = 0.f;
#pragma unroll
        for (int j = 0; j < 8; j++) {
            uint4 a = qp[j], b = kp[j];
            float2 a0 = h2f(a.x), a1 = h2f(a.y), a2 = h2f(a.z), a3 = h2f(a.w);
            float2 b0 = h2f(b.x), b1 = h2f(b.y), b2 = h2f(b.z), b3 = h2f(b.w);
            s += a0.x*b0.x + a0.y*b0.y + a1.x*b1.x + a1.y*b1.y
               + a2.x*b2.x + a2.y*b2.y + a3.x*b3.x + a3.y*b3.y;
        }
        Ss[qi][ki] = s * 0.125f;
    }
    __syncthreads();
    const int w = tid >> 5, lane = tid & 31;
    for (int qi = w; qi < 32; qi += 8) {
        float v = Ss[qi][lane];
        float m = v;
#pragma unroll
        for (int oo = 16; oo > 0; oo >>= 1) m = fmaxf(m, __shfl_xor_sync(0xffffffffu, m, oo));
        float e  = expf(v - m);
        float su = e;
#pragma unroll
        for (int oo = 16; oo > 0; oo >>= 1) su += __shfl_xor_sync(0xffffffffu, su, oo);
        Ss[qi][lane] = e / su;
    }
    __syncthreads();
    for (int i = tid; i < 1024; i += 256) {
        int f = i >> 5, d2 = i & 31;
        const float4* sp = (const float4*)Ss[f];
        float a0 = 0.f, a1 = 0.f;
#pragma unroll
        for (int k4 = 0; k4 < 8; k4++) {
            float4 sv = sp[k4];
            float2 v0 = __half22float2(Vs[k4*4+0][d2]);
            float2 v1 = __half22float2(Vs[k4*4+1][d2]);
            float2 v2 = __half22float2(Vs[k4*4+2][d2]);
            float2 v3 = __half22float2(Vs[k4*4+3][d2]);
            a0 += sv.x*v0.x + sv.y*v1.x + sv.z*v2.x + sv.w*v3.x;
            a1 += sv.x*v0.y + sv.y*v1.y + sv.z*v2.y + sv.w*v3.y;
        }
        *(u16t*)(o + (size_t)(base + f)*512 + h*64 + d2*2) = e4m3_2(a0, a1);
    }
}

// ---------------- horse attention: fp16 qkv in, fp8 out, key-masked; fp16 smem ----------------
__global__ __launch_bounds__(128)
void ha_attn_kernel(const __half* __restrict__ qkv, u8* __restrict__ o,
                    const float* __restrict__ amask)
{
    __shared__ __half2 Qs[16][36], Ks[16][36], Vs[16][36];
    __shared__ float Ss[16][20];
    const int bf = blockIdx.x;
    const int h  = blockIdx.y;
    const int b  = bf >> 5, f = bf & 31;
    const int tid = threadIdx.x;
    for (int i = tid; i < 512; i += 128) {
        int t = i >> 5, d2 = i & 31;
        size_t r = (size_t)((b*16 + t)*32 + f)*1536 + h*64 + d2*2;
        Qs[t][d2] = *(const __half2*)(qkv + r);
        Ks[t][d2] = *(const __half2*)(qkv + r + 512);
        Vs[t][d2] = *(const __half2*)(qkv + r + 1024);
    }
    __syncthreads();
    for (int i = tid; i < 256; i += 128) {
        int qi = i >> 4, ki = i & 15;
        const uint4* qp = (const uint4*)Qs[qi];
        const uint4* kp = (const uint4*)Ks[ki];
        float s = 0.f;
#pragma unroll
        for (int j = 0; j < 8; j++) {
            uint4 a = qp[j], bb = kp[j];
            float2 a0 = h2f(a.x), a1 = h2f(a.y), a2 = h2f(a.z), a3 = h2f(a.w);
            float2 b0 = h2f(bb.x), b1 = h2f(bb.y), b2 = h2f(bb.z), b3 = h2f(bb.w);
            s += a0.x*b0.x + a0.y*b0.y + a1.x*b1.x + a1.y*b1.y
               + a2.x*b2.x + a2.y*b2.y + a3.x*b3.x + a3.y*b3.y;
        }
        s *= 0.125f;
        float mk = (ki < 15) ? amask[b*15 + ki] : 1.f;
        Ss[qi][ki] = (mk > 0.f) ? s : -1e9f;
    }
    __syncthreads();
    if (tid < 16) {
        float m = -1e30f;
#pragma unroll
        for (int k = 0; k < 16; k++) m = fmaxf(m, Ss[tid][k]);
        float su = 0.f;
#pragma unroll
        for (int k = 0; k < 16; k++) { float e = expf(Ss[tid][k] - m); Ss[tid][k] = e; su += e; }
        float inv = 1.f / su;
#pragma unroll
        for (int k = 0; k < 16; k++) Ss[tid][k] *= inv;
    }
    __syncthreads();
    for (int i = tid; i < 512; i += 128) {
        int t = i >> 5, d2 = i & 31;
        const float4* sp = (const float4*)Ss[t];
        float a0 = 0.f, a1 = 0.f;
#pragma unroll
        for (int k4 = 0; k4 < 4; k4++) {
            float4 sv = sp[k4];
            float2 v0 = __half22float2(Vs[k4*4+0][d2]);
            float2 v1 = __half22float2(Vs[k4*4+1][d2]);
            float2 v2 = __half22float2(Vs[k4*4+2][d2]);
            float2 v3 = __half22float2(Vs[k4*4+3][d2]);
            a0 += sv.x*v0.x + sv.y*v1.x + sv.z*v2.x + sv.w*v3.x;
            a1 += sv.x*v0.y + sv.y*v1.y + sv.z*v2.y + sv.w*v3.y;
        }
        *(u16t*)(o + (size_t)((b*16 + t)*32 + f)*512 + h*64 + d2*2) = e4m3_2(a0, a1);
    }
}

// ---------------- pooling ----------------
__global__ __launch_bounds__(128)
void rowdot_kernel(const __half* __restrict__ T, const float* __restrict__ v,
                   float* __restrict__ out)
{
    int row = blockIdx.x, tid = threadIdx.x;
    const __half2* tr = (const __half2*)(T + (size_t)row*Dd);
    float2 a0 = __half22float2(tr[tid*2]);
    float2 a1 = __half22float2(tr[tid*2+1]);
    float4 w = ((const float4*)v)[tid];
    float s = a0.x*w.x + a0.y*w.y + a1.x*w.z + a1.y*w.w;
    s = warp_sum(s);
    __shared__ float red[4];
    if ((tid & 31) == 0) red[tid >> 5] = s;
    __syncthreads();
    if (tid == 0) out[row] = red[0]+red[1]+red[2]+red[3];
}

__global__ __launch_bounds__(256)
void pool_kernel(const float* __restrict__ s, const __half* __restrict__ seq,
                 float* __restrict__ pooled)
{
    int bt = blockIdx.x;
    int tid = threadIdx.x;
    __shared__ float aw[32];
    if (tid < 32) {
        float v = s[bt*32 + tid];
        float m = v;
#pragma unroll
        for (int o = 16; o > 0; o >>= 1) m = fmaxf(m, __shfl_xor_sync(0xffffffffu, m, o));
        float e  = expf(v - m);
        float su = e;
#pragma unroll
        for (int o = 16; o > 0; o >>= 1) su += __shfl_xor_sync(0xffffffffu, su, o);
        aw[tid] = e / su;
    }
    __syncthreads();
    int d2 = tid;
    float ax = 0.f, ay = 0.f;
#pragma unroll
    for (int f = 0; f < 32; f++) {
        float2 xf = __half22float2(*(const __half2*)(seq + ((size_t)bt*32 + f)*Dd + d2*2));
        ax += aw[f]*xf.x; ay += aw[f]*xf.y;
    }
    pooled[(size_t)bt*Dd + d2*2]     = ax;
    pooled[(size_t)bt*Dd + d2*2 + 1] = ay;
}

__global__ __launch_bounds__(256)
void combine_kernel(const float* __restrict__ pooled, u8* __restrict__ comb)
{
    int idx = blockIdx.x*256 + threadIdx.x;
    int bh = idx >> 9;
    int c  = (idx & 511) * 2;
    int b = bh / 15, h = bh % 15;
    float2 p;
    if (c < 512) p = *(const float2*)(pooled + (b*16 + h)*Dd + c);
    else         p = *(const float2*)(pooled + (b*16 + 15)*Dd + (c - 512));
    ((u16t*)comb)[idx] = e4m3_2(p.x, p.y);
}

__global__ __launch_bounds__(256)
void maskmul_kernel(const float* __restrict__ feat, const float* __restrict__ amask,
                    u8* __restrict__ feat8)
{
    int idx = blockIdx.x*256 + threadIdx.x;
    float2 p = *(const float2*)(feat + idx*2);
    float mk = amask[idx >> 8];
    ((u16t*)feat8)[idx] = e4m3_2(p.x*mk, p.y*mk);
}

// ---------------- MCMC ----------------
__global__ __launch_bounds__(512)
void mcmc_kernel(const float* __restrict__ U, const float* __restrict__ e_w1,
                 const float* __restrict__ e_w2, const float* __restrict__ amask,
                 const float* __restrict__ pred0, const int* __restrict__ nsteps,
                 float* __restrict__ out)
{
    const int bh = blockIdx.x;
    const int b  = bh / 15;
    const int j  = threadIdx.x;
    const float u  = U[(size_t)bh*Dd + j];
    const float wj = e_w1[512*512 + j];
    const float wc = wj * e_w2[j];
    const float mk = amask[bh];
    __shared__ float red[16];
    __shared__ float sp, shpr;
    if (j == 0) {
        float s = 0.f;
        for (int i = 0; i < 15; i++) s += amask[b*15 + i];
        shpr = s;
        sp = pred0[bh];
    }
    __syncthreads();
    const int n = *nsteps;
    for (int st = 0; st < n; st++) {
        float p = sp;
        float a = u + p*wj;
        float v = gelu_grad(a) * wc;
        v = warp_sum(v);
        if ((j & 31) == 0) red[j >> 5] = v;
        __syncthreads();
        if (j == 0) {
            float de = 0.f;
#pragma unroll
            for (int w = 0; w < 16; w++) de += red[w];
            float dent = -( logf(p + EPSc) + p/(p + EPSc)
                          - logf(1.f - p + EPSc) - (1.f - p)/(1.f - p + EPSc) );
            float g = (mk/(shpr*64.f)) * (de - 0.05f*dent);
            p = p - 0.1f*g*mk;
            p = (tanhf(p - 0.5f) + 1.f)*0.5f*(1.f - 2e-7f) + 1e-7f;
            p = fminf(fmaxf(p, EPSc), 1.f - EPSc);
            sp = p;
        }
        __syncthreads();
    }
    if (j == 0) out[bh] = sp;
}

// ---------------- host launch ----------------
static void launch_qgemm(int act, int cout, const u8* A, const u8* Wt, void* C,
                         int M, int N, int K, const float* bias, int accum, u8* c8dup)
{
    dim3 grid(N/128, (M + 127)/128);
    if (cout == 1) {
        if (act == 0) {
            cudaFuncSetAttribute(qgemm_kernel<0,1>, cudaFuncAttributeMaxDynamicSharedMemorySize, GSM_B);
            qgemm_kernel<0,1><<<grid, 128, GSM_B>>>(A, Wt, C, M, N, K, bias, accum, c8dup);
        } else if (act == 2) {
            cudaFuncSetAttribute(qgemm_kernel<2,1>, cudaFuncAttributeMaxDynamicSharedMemorySize, GSM_B);
            qgemm_kernel<2,1><<<grid, 128, GSM_B>>>(A, Wt, C, M, N, K, bias, accum, c8dup);
        } else {
            cudaFuncSetAttribute(qgemm_kernel<1,1>, cudaFuncAttributeMaxDynamicSharedMemorySize, GSM_B);
            qgemm_kernel<1,1><<<grid, 128, GSM_B>>>(A, Wt, C, M, N, K, bias, accum, c8dup);
        }
    } else if (cout == 2) {
        cudaFuncSetAttribute(qgemm_kernel<1,2>, cudaFuncAttributeMaxDynamicSharedMemorySize, GSM_B);
        qgemm_kernel<1,2><<<grid, 128, GSM_B>>>(A, Wt, C, M, N, K, bias, accum, nullptr);
    } else {
        cudaFuncSetAttribute(qgemm_kernel<0,0>, cudaFuncAttributeMaxDynamicSharedMemorySize, GSM_B);
        qgemm_kernel<0,0><<<grid, 128, GSM_B>>>(A, Wt, C, M, N, K, bias, accum, nullptr);
    }
}
static void launch_wcvt2(const float* in0, u8* out0, const float* in1, u8* out1,
                         int K, int N, int L0, int L1)
{
    dim3 grid(N/32, K/32, L0 + L1);
    wcvt_kernel<<<grid, 256>>>(in0, out0, in1, out1, K, N, L0);
}

extern "C" void kernel_launch(void* const* d_in, const int* in_sizes, int n_in,
                              void* d_out, int out_size)
{
    const float* x_cont  = (const float*)d_in[0];
    const int*   x_cat   = (const int*)  d_in[1];
    const float* amask   = (const float*)d_in[2];
    const float* pred0   = (const float*)d_in[3];
    const float* emb_w   = (const float*)d_in[4];
    const float* emb_b   = (const float*)d_in[5];
    const float* cat_emb = (const float*)d_in[6];
    const float* cls     = (const float*)d_in[7];
    const float* fa_wqkv = (const float*)d_in[8];
    const float* fa_wo   = (const float*)d_in[9];
    const float* ha_wqkv = (const float*)d_in[10];
    const float* ha_wo   = (const float*)d_in[11];
    const float* ffn_w1  = (const float*)d_in[12];
    const float* ffn_b1  = (const float*)d_in[13];
    const float* ffn_w2  = (const float*)d_in[14];
    const float* ffn_b2  = (const float*)d_in[15];
    const float* ln1_g   = (const float*)d_in[16];
    const float* ln1_b   = (const float*)d_in[17];
    const float* ln2_g   = (const float*)d_in[18];
    const float* ln2_b   = (const float*)d_in[19];
    const float* ln3_g   = (const float*)d_in[20];
    const float* ln3_b   = (const float*)d_in[21];
    const float* pool_w  = (const float*)d_in[22];
    const float* pool_b  = (const float*)d_in[23];
    const float* pool_v  = (const float*)d_in[24];
    const float* proj_w  = (const float*)d_in[25];
    const float* proj_b  = (const float*)d_in[26];
    const float* e_w1    = (const float*)d_in[27];
    const float* e_b1    = (const float*)d_in[28];
    const float* e_w2    = (const float*)d_in[29];
    const int*   nsteps  = (const int*)  d_in[31];
    float* out = (float*)d_out;

    float *sbuf, *pool, *feat, *ubuf;
    __half *seqh, *qkvh;
    u8 *a8, *f8, *w8, *comb8, *feat8;
    cudaGetSymbolAddress((void**)&seqh, g_seqh);
    cudaGetSymbolAddress((void**)&qkvh, g_qkvh);
    cudaGetSymbolAddress((void**)&a8,   g_a8);
    cudaGetSymbolAddress((void**)&f8,   g_f8);
    cudaGetSymbolAddress((void**)&w8,   g_w8);
    cudaGetSymbolAddress((void**)&sbuf, g_s);
    cudaGetSymbolAddress((void**)&pool, g_pool);
    cudaGetSymbolAddress((void**)&comb8,g_comb8);
    cudaGetSymbolAddress((void**)&feat, g_feat);
    cudaGetSymbolAddress((void**)&feat8,g_feat8);
    cudaGetSymbolAddress((void**)&ubuf, g_u);

    // launch order: #4 is the hot QKV GEMM (for ncu -s capture)
    embed_kernel<<<(NTOK*Dd/2)/256, 256>>>(x_cont, x_cat, emb_w, emb_b, cat_emb, cls, seqh);
    ln2_kernel<<<NTOK/8, 256>>>(seqh, a8, ln1_g, ln1_b);
    launch_wcvt2(fa_wqkv, w8 + OFF_FAQKV, ha_wqkv, w8 + OFF_HAQKV, 512, 1536, 4, 4);
    launch_qgemm(0, 1, a8, w8 + OFF_FAQKV, qkvh, NTOK, 3*Dd, Dd, nullptr, 0, nullptr);

    // deferred weight conversions
    launch_wcvt2(fa_wo,  w8 + OFF_FAWO, ha_wo, w8 + OFF_HAWO, 512, 512, 4, 4);
    launch_wcvt2(ffn_w1, w8 + OFF_FFN1, ffn_w1, w8 + OFF_FFN1, 512, 2048, 4, 0);
    launch_wcvt2(ffn_w2, w8 + OFF_FFN2, ffn_w2, w8 + OFF_FFN2, 2048, 512, 4, 0);
    launch_wcvt2(pool_w, w8 + OFF_POOLW, e_w1, w8 + OFF_EW1,   512, 512,  1, 1);
    launch_wcvt2(proj_w, w8 + OFF_PROJW, proj_w, w8 + OFF_PROJW, 1024, 512, 1, 0);

    for (int l = 0; l < Ll; l++) {
        if (l > 0) {
            ln2_kernel<<<NTOK/8, 256>>>(seqh, a8, ln1_g + l*Dd, ln1_b + l*Dd);
            launch_qgemm(0, 1, a8, w8 + OFF_FAQKV + (size_t)l*512*1536, qkvh, NTOK, 3*Dd, Dd, nullptr, 0, nullptr);
        }
        fa_attn_kernel<<<dim3(Bb*Tt, NHh), 256>>>(qkvh, a8);
        launch_qgemm(0, 1, a8, w8 + OFF_FAWO + (size_t)l*512*512, seqh, NTOK, Dd, Dd, nullptr, 1, nullptr);

        ln2_kernel<<<NTOK/8, 256>>>(seqh, a8, ln2_g + l*Dd, ln2_b + l*Dd);
        launch_qgemm(0, 1, a8, w8 + OFF_HAQKV + (size_t)l*512*1536, qkvh, NTOK, 3*Dd, Dd, nullptr, 0, nullptr);
        ha_attn_kernel<<<dim3(Bb*Ff, NHh), 128>>>(qkvh, a8, amask);
        launch_qgemm(0, 1, a8, w8 + OFF_HAWO + (size_t)l*512*512, seqh, NTOK, Dd, Dd, nullptr, 1, nullptr);

        ln2_kernel<<<NTOK/8, 256>>>(seqh, a8, ln3_g + l*Dd, ln3_b + l*Dd);
        launch_qgemm(1, 2, a8, w8 + OFF_FFN1 + (size_t)l*512*2048, f8, NTOK, DFFf, Dd, ffn_b1 + l*DFFf, 0, nullptr);
        launch_qgemm(0, 1, f8, w8 + OFF_FFN2 + (size_t)l*512*2048, seqh, NTOK, Dd, DFFf, ffn_b2 + l*Dd, 1,
                     (l == Ll-1) ? a8 : nullptr);
    }

    // attention pooling
    launch_qgemm(2, 1, a8, w8 + OFF_POOLW, qkvh, NTOK, Dd, Dd, pool_b, 0, nullptr);
    rowdot_kernel<<<NTOK, 128>>>(qkvh, pool_v, sbuf);
    pool_kernel<<<Bb*Tt, 256>>>(sbuf, seqh, pool);
    combine_kernel<<<(Bb*Hh*512)/256, 256>>>(pool, comb8);
    launch_qgemm(0, 0, comb8, w8 + OFF_PROJW, feat, Bb*Hh, Dd, 2*Dd, proj_b, 0, nullptr);
    maskmul_kernel<<<(Bb*Hh*256)/256, 256>>>(feat, amask, feat8);

    // energy precompute
    launch_qgemm(0, 0, feat8, w8 + OFF_EW1, ubuf, Bb*Hh, Dd, Dd, e_b1, 0, nullptr);

    // MCMC
    mcmc_kernel<<<Bb*Hh, 512>>>(ubuf, e_w1, e_w2, amask, pred0, nsteps, out);
}